// round 2
// baseline (speedup 1.0000x reference)
#include <cuda_runtime.h>
#include <cuda_bf16.h>

// Problem constants
#define BATCH 2
#define SEQ   2048
#define CDIM  1024
#define HEADS 16
#define HDIM  64
#define QKV_N (3*CDIM)
#define MROWS (BATCH*SEQ)          // 4096
#define ATT_SCALE 0.125f           // 64^-0.5

// Scratch (device globals; no allocation allowed)
__device__ float g_q[BATCH*HEADS*SEQ*HDIM];   // [B,H,N,D], pre-scaled by ATT_SCALE
__device__ float g_k[BATCH*HEADS*SEQ*HDIM];
__device__ float g_v[BATCH*HEADS*SEQ*HDIM];
__device__ float g_att[BATCH*SEQ*CDIM];       // [B,N,C] attention output

// ---------------------------------------------------------------------------
// Kernel 1: QKV GEMM.  X[4096,1024] @ Wqkv[1024,3072] -> scatter to q/k/v.
// 64x64 tile, BK=16, 256 threads, 4x4 per thread.
// ---------------------------------------------------------------------------
__global__ __launch_bounds__(256) void qkv_gemm(const float* __restrict__ X,
                                                const float* __restrict__ W) {
    __shared__ float As[16][68];   // As[k][m]
    __shared__ float Bs[16][68];   // Bs[k][n]
    const int tid = threadIdx.x;
    const int tx = tid & 15, ty = tid >> 4;
    const int row0 = blockIdx.y * 64;
    const int col0 = blockIdx.x * 64;

    const int am = tid >> 2;           // 0..63
    const int ak = (tid & 3) * 4;      // 0,4,8,12
    const int bk = tid >> 4;           // 0..15
    const int bn = (tid & 15) * 4;     // 0..60

    float acc[4][4] = {};

    for (int k0 = 0; k0 < CDIM; k0 += 16) {
        float4 a = *(const float4*)&X[(row0 + am) * CDIM + k0 + ak];
        As[ak + 0][am] = a.x; As[ak + 1][am] = a.y;
        As[ak + 2][am] = a.z; As[ak + 3][am] = a.w;
        *(float4*)&Bs[bk][bn] = *(const float4*)&W[(k0 + bk) * QKV_N + col0 + bn];
        __syncthreads();
#pragma unroll
        for (int k = 0; k < 16; k++) {
            float4 ra = *(float4*)&As[k][ty * 4];
            float4 rb = *(float4*)&Bs[k][tx * 4];
            acc[0][0] += ra.x * rb.x; acc[0][1] += ra.x * rb.y; acc[0][2] += ra.x * rb.z; acc[0][3] += ra.x * rb.w;
            acc[1][0] += ra.y * rb.x; acc[1][1] += ra.y * rb.y; acc[1][2] += ra.y * rb.z; acc[1][3] += ra.y * rb.w;
            acc[2][0] += ra.z * rb.x; acc[2][1] += ra.z * rb.y; acc[2][2] += ra.z * rb.z; acc[2][3] += ra.z * rb.w;
            acc[3][0] += ra.w * rb.x; acc[3][1] += ra.w * rb.y; acc[3][2] += ra.w * rb.z; acc[3][3] += ra.w * rb.w;
        }
        __syncthreads();
    }

#pragma unroll
    for (int i = 0; i < 4; i++) {
        const int r = row0 + ty * 4 + i;
        const int b = r >> 11;             // r / SEQ
        const int n = r & (SEQ - 1);
#pragma unroll
        for (int j = 0; j < 4; j++) {
            const int c = col0 + tx * 4 + j;
            const int sel = c >> 10;       // 0=q,1=k,2=v
            const int rr  = c & 1023;
            const int h   = rr >> 6;
            const int d   = rr & 63;
            const int idx = ((b * HEADS + h) * SEQ + n) * HDIM + d;
            const float v = acc[i][j];
            if (sel == 0)      g_q[idx] = v * ATT_SCALE;
            else if (sel == 1) g_k[idx] = v;
            else               g_v[idx] = v;
        }
    }
}

// ---------------------------------------------------------------------------
// Kernel 2: flash attention (fp32, online softmax).
// Block: 64 query rows of one (b,h); loop over 32 key tiles of 64.
// Smem: Qst[d][r], KV (K as [d][c], then V as [k][d]), Sst[c][r]  (pad 68).
// ---------------------------------------------------------------------------
__global__ __launch_bounds__(256) void attn_kernel() {
    extern __shared__ float sm[];
    float* Qst  = sm;                 // 64*68
    float* KV   = sm + 64 * 68;       // 64*68
    float* Sst  = sm + 2 * 64 * 68;   // 64*68
    float* mrow = sm + 3 * 64 * 68;   // 64
    float* lrow = mrow + 64;          // 64
    float* frow = lrow + 64;          // 64
    float* red  = frow + 64;          // 64*4

    const int tid = threadIdx.x;
    const int tx = tid & 15, ty = tid >> 4;
    const int bh = blockIdx.y;                // b*HEADS + h
    const int q0 = blockIdx.x * 64;

    const float* Qg  = g_q + (bh * SEQ + q0) * HDIM;
    const float* Kg0 = g_k + bh * SEQ * HDIM;
    const float* Vg0 = g_v + bh * SEQ * HDIM;

    if (tid < 64) { mrow[tid] = -1e30f; lrow[tid] = 0.f; }

    // Load Q tile transposed: Qst[d*68 + r]
    {
        const int r  = tid >> 2;
        const int db = (tid & 3) * 16;
#pragma unroll
        for (int i = 0; i < 4; i++) {
            const int d = db + i * 4;
            float4 v = *(const float4*)&Qg[r * HDIM + d];
            Qst[(d + 0) * 68 + r] = v.x;
            Qst[(d + 1) * 68 + r] = v.y;
            Qst[(d + 2) * 68 + r] = v.z;
            Qst[(d + 3) * 68 + r] = v.w;
        }
    }

    float o[4][4] = {};
    const int r0 = ty * 4, c0 = tx * 4;

    for (int kt = 0; kt < SEQ / 64; kt++) {
        const float* Kg = Kg0 + kt * 64 * HDIM;
        const float* Vg = Vg0 + kt * 64 * HDIM;

        // Load K tile transposed: KV[d*68 + c]
        {
            const int c  = tid >> 2;
            const int db = (tid & 3) * 16;
#pragma unroll
            for (int i = 0; i < 4; i++) {
                const int d = db + i * 4;
                float4 v = *(const float4*)&Kg[c * HDIM + d];
                KV[(d + 0) * 68 + c] = v.x;
                KV[(d + 1) * 68 + c] = v.y;
                KV[(d + 2) * 68 + c] = v.z;
                KV[(d + 3) * 68 + c] = v.w;
            }
        }
        __syncthreads();

        // S = Q @ K^T  (Q pre-scaled); write Sst[c*68 + r]
        {
            float s[4][4] = {};
#pragma unroll 8
            for (int k = 0; k < 64; k++) {
                float4 rq = *(float4*)&Qst[k * 68 + r0];
                float4 rk = *(float4*)&KV [k * 68 + c0];
                s[0][0] += rq.x * rk.x; s[0][1] += rq.x * rk.y; s[0][2] += rq.x * rk.z; s[0][3] += rq.x * rk.w;
                s[1][0] += rq.y * rk.x; s[1][1] += rq.y * rk.y; s[1][2] += rq.y * rk.z; s[1][3] += rq.y * rk.w;
                s[2][0] += rq.z * rk.x; s[2][1] += rq.z * rk.y; s[2][2] += rq.z * rk.z; s[2][3] += rq.z * rk.w;
                s[3][0] += rq.w * rk.x; s[3][1] += rq.w * rk.y; s[3][2] += rq.w * rk.z; s[3][3] += rq.w * rk.w;
            }
#pragma unroll
            for (int j = 0; j < 4; j++)
#pragma unroll
                for (int i = 0; i < 4; i++)
                    Sst[(c0 + j) * 68 + (r0 + i)] = s[i][j];
        }
        __syncthreads();

        // Load V tile (plain [k][d]) into KV, plus per-row max partials
        {
            const int kr = tid >> 2;
            const int db = (tid & 3) * 16;
#pragma unroll
            for (int i = 0; i < 4; i++)
                *(float4*)&KV[kr * 68 + db + i * 4] =
                    *(const float4*)&Vg[kr * HDIM + db + i * 4];
        }
        {
            const int r = tid & 63, qtr = tid >> 6;
            float mx = -1e30f;
#pragma unroll
            for (int t = 0; t < 16; t++)
                mx = fmaxf(mx, Sst[(qtr * 16 + t) * 68 + r]);
            red[r * 4 + qtr] = mx;
        }
        __syncthreads();

        if (tid < 64) {
            float tm = fmaxf(fmaxf(red[tid * 4], red[tid * 4 + 1]),
                             fmaxf(red[tid * 4 + 2], red[tid * 4 + 3]));
            float nm = fmaxf(mrow[tid], tm);
            frow[tid] = __expf(mrow[tid] - nm);
            mrow[tid] = nm;
        }
        __syncthreads();

        // P = exp(S - m) in place; partial row sums
        {
            const int r = tid & 63, qtr = tid >> 6;
            const float nm = mrow[r];
            float sum = 0.f;
#pragma unroll
            for (int t = 0; t < 16; t++) {
                const int idx = (qtr * 16 + t) * 68 + r;
                float p = __expf(Sst[idx] - nm);
                Sst[idx] = p;
                sum += p;
            }
            red[r * 4 + qtr] = sum;
        }
        __syncthreads();

        if (tid < 64)
            lrow[tid] = lrow[tid] * frow[tid] +
                        red[tid * 4] + red[tid * 4 + 1] + red[tid * 4 + 2] + red[tid * 4 + 3];

        // Rescale accumulators, then O += P @ V
        {
            const float f0 = frow[r0], f1 = frow[r0 + 1], f2 = frow[r0 + 2], f3 = frow[r0 + 3];
#pragma unroll
            for (int j = 0; j < 4; j++) {
                o[0][j] *= f0; o[1][j] *= f1; o[2][j] *= f2; o[3][j] *= f3;
            }
#pragma unroll 8
            for (int k = 0; k < 64; k++) {
                float4 p = *(float4*)&Sst[k * 68 + r0];
                float4 v = *(float4*)&KV [k * 68 + c0];
                o[0][0] += p.x * v.x; o[0][1] += p.x * v.y; o[0][2] += p.x * v.z; o[0][3] += p.x * v.w;
                o[1][0] += p.y * v.x; o[1][1] += p.y * v.y; o[1][2] += p.y * v.z; o[1][3] += p.y * v.w;
                o[2][0] += p.z * v.x; o[2][1] += p.z * v.y; o[2][2] += p.z * v.z; o[2][3] += p.z * v.w;
                o[3][0] += p.w * v.x; o[3][1] += p.w * v.y; o[3][2] += p.w * v.z; o[3][3] += p.w * v.w;
            }
        }
        __syncthreads();
    }

    // Write normalized output: g_att[b,n, h*64 + d]
    const int b = bh >> 4, h = bh & 15;
#pragma unroll
    for (int i = 0; i < 4; i++) {
        const int n = q0 + r0 + i;
        const float inv = 1.f / lrow[r0 + i];
        float* dst = &g_att[(b * SEQ + n) * CDIM + h * HDIM + c0];
        dst[0] = o[i][0] * inv;
        dst[1] = o[i][1] * inv;
        dst[2] = o[i][2] * inv;
        dst[3] = o[i][3] * inv;
    }
}

// ---------------------------------------------------------------------------
// Kernel 3: projection GEMM + bias.  g_att[4096,1024] @ Wp[1024,1024] + b.
// ---------------------------------------------------------------------------
__global__ __launch_bounds__(256) void proj_gemm(const float* __restrict__ W,
                                                 const float* __restrict__ bias,
                                                 float* __restrict__ out) {
    __shared__ float As[16][68];
    __shared__ float Bs[16][68];
    const int tid = threadIdx.x;
    const int tx = tid & 15, ty = tid >> 4;
    const int row0 = blockIdx.y * 64;
    const int col0 = blockIdx.x * 64;

    const int am = tid >> 2;
    const int ak = (tid & 3) * 4;
    const int bk = tid >> 4;
    const int bn = (tid & 15) * 4;

    float acc[4][4] = {};

    for (int k0 = 0; k0 < CDIM; k0 += 16) {
        float4 a = *(const float4*)&g_att[(row0 + am) * CDIM + k0 + ak];
        As[ak + 0][am] = a.x; As[ak + 1][am] = a.y;
        As[ak + 2][am] = a.z; As[ak + 3][am] = a.w;
        *(float4*)&Bs[bk][bn] = *(const float4*)&W[(k0 + bk) * CDIM + col0 + bn];
        __syncthreads();
#pragma unroll
        for (int k = 0; k < 16; k++) {
            float4 ra = *(float4*)&As[k][ty * 4];
            float4 rb = *(float4*)&Bs[k][tx * 4];
            acc[0][0] += ra.x * rb.x; acc[0][1] += ra.x * rb.y; acc[0][2] += ra.x * rb.z; acc[0][3] += ra.x * rb.w;
            acc[1][0] += ra.y * rb.x; acc[1][1] += ra.y * rb.y; acc[1][2] += ra.y * rb.z; acc[1][3] += ra.y * rb.w;
            acc[2][0] += ra.z * rb.x; acc[2][1] += ra.z * rb.y; acc[2][2] += ra.z * rb.z; acc[2][3] += ra.z * rb.w;
            acc[3][0] += ra.w * rb.x; acc[3][1] += ra.w * rb.y; acc[3][2] += ra.w * rb.z; acc[3][3] += ra.w * rb.w;
        }
        __syncthreads();
    }

#pragma unroll
    for (int i = 0; i < 4; i++) {
        const int r = row0 + ty * 4 + i;
#pragma unroll
        for (int j = 0; j < 4; j++) {
            const int c = col0 + tx * 4 + j;
            out[r * CDIM + c] = acc[i][j] + bias[c];
        }
    }
}

// ---------------------------------------------------------------------------
extern "C" void kernel_launch(void* const* d_in, const int* in_sizes, int n_in,
                              void* d_out, int out_size) {
    const float* x      = (const float*)d_in[0];
    const float* w_qkv  = (const float*)d_in[1];
    const float* w_proj = (const float*)d_in[2];
    const float* b_proj = (const float*)d_in[3];
    float* out = (float*)d_out;

    (void)in_sizes; (void)n_in; (void)out_size;

    const size_t attn_smem = (3 * 64 * 68 + 3 * 64 + 64 * 4) * sizeof(float);
    cudaFuncSetAttribute(attn_kernel, cudaFuncAttributeMaxDynamicSharedMemorySize,
                         (int)attn_smem);

    qkv_gemm<<<dim3(QKV_N / 64, MROWS / 64), 256>>>(x, w_qkv);
    attn_kernel<<<dim3(SEQ / 64, BATCH * HEADS), 256, attn_smem>>>();
    proj_gemm<<<dim3(CDIM / 64, MROWS / 64), 256>>>(w_proj, b_proj, out);
}

// round 3
// speedup vs baseline: 1.0001x; 1.0001x over previous
#include <cuda_runtime.h>
#include <cuda_bf16.h>

// Problem constants
#define BATCH 2
#define SEQ   2048
#define CDIM  1024
#define HEADS 16
#define HDIM  64
#define QKV_N (3*CDIM)
#define MROWS (BATCH*SEQ)          // 4096
#define ATT_SCALE 0.125f           // 64^-0.5

// Scratch (device globals; no allocation allowed)
__device__ float g_q[BATCH*HEADS*SEQ*HDIM];   // [B,H,N,D], pre-scaled by ATT_SCALE
__device__ float g_k[BATCH*HEADS*SEQ*HDIM];
__device__ float g_v[BATCH*HEADS*SEQ*HDIM];
__device__ float g_att[BATCH*SEQ*CDIM];       // [B,N,C] attention output

// ---------------------------------------------------------------------------
// Kernel 1: QKV GEMM.  X[4096,1024] @ Wqkv[1024,3072] -> scatter to q/k/v.
// 64x64 tile, BK=16, 256 threads, 4x4 per thread.
// ---------------------------------------------------------------------------
__global__ __launch_bounds__(256) void qkv_gemm(const float* __restrict__ X,
                                                const float* __restrict__ W) {
    __shared__ float As[16][68];   // As[k][m]
    __shared__ float Bs[16][68];   // Bs[k][n]
    const int tid = threadIdx.x;
    const int tx = tid & 15, ty = tid >> 4;
    const int row0 = blockIdx.y * 64;
    const int col0 = blockIdx.x * 64;

    const int am = tid >> 2;           // 0..63
    const int ak = (tid & 3) * 4;      // 0,4,8,12
    const int bk = tid >> 4;           // 0..15
    const int bn = (tid & 15) * 4;     // 0..60

    float acc[4][4] = {};

    for (int k0 = 0; k0 < CDIM; k0 += 16) {
        float4 a = *(const float4*)&X[(row0 + am) * CDIM + k0 + ak];
        As[ak + 0][am] = a.x; As[ak + 1][am] = a.y;
        As[ak + 2][am] = a.z; As[ak + 3][am] = a.w;
        *(float4*)&Bs[bk][bn] = *(const float4*)&W[(k0 + bk) * QKV_N + col0 + bn];
        __syncthreads();
#pragma unroll
        for (int k = 0; k < 16; k++) {
            float4 ra = *(float4*)&As[k][ty * 4];
            float4 rb = *(float4*)&Bs[k][tx * 4];
            acc[0][0] += ra.x * rb.x; acc[0][1] += ra.x * rb.y; acc[0][2] += ra.x * rb.z; acc[0][3] += ra.x * rb.w;
            acc[1][0] += ra.y * rb.x; acc[1][1] += ra.y * rb.y; acc[1][2] += ra.y * rb.z; acc[1][3] += ra.y * rb.w;
            acc[2][0] += ra.z * rb.x; acc[2][1] += ra.z * rb.y; acc[2][2] += ra.z * rb.z; acc[2][3] += ra.z * rb.w;
            acc[3][0] += ra.w * rb.x; acc[3][1] += ra.w * rb.y; acc[3][2] += ra.w * rb.z; acc[3][3] += ra.w * rb.w;
        }
        __syncthreads();
    }

#pragma unroll
    for (int i = 0; i < 4; i++) {
        const int r = row0 + ty * 4 + i;
        const int b = r >> 11;             // r / SEQ
        const int n = r & (SEQ - 1);
#pragma unroll
        for (int j = 0; j < 4; j++) {
            const int c = col0 + tx * 4 + j;
            const int sel = c >> 10;       // 0=q,1=k,2=v
            const int rr  = c & 1023;
            const int h   = rr >> 6;
            const int d   = rr & 63;
            const int idx = ((b * HEADS + h) * SEQ + n) * HDIM + d;
            const float v = acc[i][j];
            if (sel == 0)      g_q[idx] = v * ATT_SCALE;
            else if (sel == 1) g_k[idx] = v;
            else               g_v[idx] = v;
        }
    }
}

// ---------------------------------------------------------------------------
// Kernel 2: flash attention (fp32, online softmax).
// Block: 64 query rows of one (b,h); loop over 32 key tiles of 64.
// Smem: Qst[d][r], KV (K as [d][c], then V as [k][d]), Sst[c][r]  (pad 68).
// ---------------------------------------------------------------------------
__global__ __launch_bounds__(256) void attn_kernel() {
    extern __shared__ float sm[];
    float* Qst  = sm;                 // 64*68
    float* KV   = sm + 64 * 68;       // 64*68
    float* Sst  = sm + 2 * 64 * 68;   // 64*68
    float* mrow = sm + 3 * 64 * 68;   // 64
    float* lrow = mrow + 64;          // 64
    float* frow = lrow + 64;          // 64
    float* red  = frow + 64;          // 64*4

    const int tid = threadIdx.x;
    const int tx = tid & 15, ty = tid >> 4;
    const int bh = blockIdx.y;                // b*HEADS + h
    const int q0 = blockIdx.x * 64;

    const float* Qg  = g_q + (bh * SEQ + q0) * HDIM;
    const float* Kg0 = g_k + bh * SEQ * HDIM;
    const float* Vg0 = g_v + bh * SEQ * HDIM;

    if (tid < 64) { mrow[tid] = -1e30f; lrow[tid] = 0.f; }

    // Load Q tile transposed: Qst[d*68 + r]
    {
        const int r  = tid >> 2;
        const int db = (tid & 3) * 16;
#pragma unroll
        for (int i = 0; i < 4; i++) {
            const int d = db + i * 4;
            float4 v = *(const float4*)&Qg[r * HDIM + d];
            Qst[(d + 0) * 68 + r] = v.x;
            Qst[(d + 1) * 68 + r] = v.y;
            Qst[(d + 2) * 68 + r] = v.z;
            Qst[(d + 3) * 68 + r] = v.w;
        }
    }

    float o[4][4] = {};
    const int r0 = ty * 4, c0 = tx * 4;

    for (int kt = 0; kt < SEQ / 64; kt++) {
        const float* Kg = Kg0 + kt * 64 * HDIM;
        const float* Vg = Vg0 + kt * 64 * HDIM;

        // Load K tile transposed: KV[d*68 + c]
        {
            const int c  = tid >> 2;
            const int db = (tid & 3) * 16;
#pragma unroll
            for (int i = 0; i < 4; i++) {
                const int d = db + i * 4;
                float4 v = *(const float4*)&Kg[c * HDIM + d];
                KV[(d + 0) * 68 + c] = v.x;
                KV[(d + 1) * 68 + c] = v.y;
                KV[(d + 2) * 68 + c] = v.z;
                KV[(d + 3) * 68 + c] = v.w;
            }
        }
        __syncthreads();

        // S = Q @ K^T  (Q pre-scaled); write Sst[c*68 + r]
        {
            float s[4][4] = {};
#pragma unroll 8
            for (int k = 0; k < 64; k++) {
                float4 rq = *(float4*)&Qst[k * 68 + r0];
                float4 rk = *(float4*)&KV [k * 68 + c0];
                s[0][0] += rq.x * rk.x; s[0][1] += rq.x * rk.y; s[0][2] += rq.x * rk.z; s[0][3] += rq.x * rk.w;
                s[1][0] += rq.y * rk.x; s[1][1] += rq.y * rk.y; s[1][2] += rq.y * rk.z; s[1][3] += rq.y * rk.w;
                s[2][0] += rq.z * rk.x; s[2][1] += rq.z * rk.y; s[2][2] += rq.z * rk.z; s[2][3] += rq.z * rk.w;
                s[3][0] += rq.w * rk.x; s[3][1] += rq.w * rk.y; s[3][2] += rq.w * rk.z; s[3][3] += rq.w * rk.w;
            }
#pragma unroll
            for (int j = 0; j < 4; j++)
#pragma unroll
                for (int i = 0; i < 4; i++)
                    Sst[(c0 + j) * 68 + (r0 + i)] = s[i][j];
        }
        __syncthreads();

        // Load V tile (plain [k][d]) into KV, plus per-row max partials
        {
            const int kr = tid >> 2;
            const int db = (tid & 3) * 16;
#pragma unroll
            for (int i = 0; i < 4; i++)
                *(float4*)&KV[kr * 68 + db + i * 4] =
                    *(const float4*)&Vg[kr * HDIM + db + i * 4];
        }
        {
            const int r = tid & 63, qtr = tid >> 6;
            float mx = -1e30f;
#pragma unroll
            for (int t = 0; t < 16; t++)
                mx = fmaxf(mx, Sst[(qtr * 16 + t) * 68 + r]);
            red[r * 4 + qtr] = mx;
        }
        __syncthreads();

        if (tid < 64) {
            float tm = fmaxf(fmaxf(red[tid * 4], red[tid * 4 + 1]),
                             fmaxf(red[tid * 4 + 2], red[tid * 4 + 3]));
            float nm = fmaxf(mrow[tid], tm);
            frow[tid] = __expf(mrow[tid] - nm);
            mrow[tid] = nm;
        }
        __syncthreads();

        // P = exp(S - m) in place; partial row sums
        {
            const int r = tid & 63, qtr = tid >> 6;
            const float nm = mrow[r];
            float sum = 0.f;
#pragma unroll
            for (int t = 0; t < 16; t++) {
                const int idx = (qtr * 16 + t) * 68 + r;
                float p = __expf(Sst[idx] - nm);
                Sst[idx] = p;
                sum += p;
            }
            red[r * 4 + qtr] = sum;
        }
        __syncthreads();

        if (tid < 64)
            lrow[tid] = lrow[tid] * frow[tid] +
                        red[tid * 4] + red[tid * 4 + 1] + red[tid * 4 + 2] + red[tid * 4 + 3];

        // Rescale accumulators, then O += P @ V
        {
            const float f0 = frow[r0], f1 = frow[r0 + 1], f2 = frow[r0 + 2], f3 = frow[r0 + 3];
#pragma unroll
            for (int j = 0; j < 4; j++) {
                o[0][j] *= f0; o[1][j] *= f1; o[2][j] *= f2; o[3][j] *= f3;
            }
#pragma unroll 8
            for (int k = 0; k < 64; k++) {
                float4 p = *(float4*)&Sst[k * 68 + r0];
                float4 v = *(float4*)&KV [k * 68 + c0];
                o[0][0] += p.x * v.x; o[0][1] += p.x * v.y; o[0][2] += p.x * v.z; o[0][3] += p.x * v.w;
                o[1][0] += p.y * v.x; o[1][1] += p.y * v.y; o[1][2] += p.y * v.z; o[1][3] += p.y * v.w;
                o[2][0] += p.z * v.x; o[2][1] += p.z * v.y; o[2][2] += p.z * v.z; o[2][3] += p.z * v.w;
                o[3][0] += p.w * v.x; o[3][1] += p.w * v.y; o[3][2] += p.w * v.z; o[3][3] += p.w * v.w;
            }
        }
        __syncthreads();
    }

    // Write normalized output: g_att[b,n, h*64 + d]
    const int b = bh >> 4, h = bh & 15;
#pragma unroll
    for (int i = 0; i < 4; i++) {
        const int n = q0 + r0 + i;
        const float inv = 1.f / lrow[r0 + i];
        float* dst = &g_att[(b * SEQ + n) * CDIM + h * HDIM + c0];
        dst[0] = o[i][0] * inv;
        dst[1] = o[i][1] * inv;
        dst[2] = o[i][2] * inv;
        dst[3] = o[i][3] * inv;
    }
}

// ---------------------------------------------------------------------------
// Kernel 3: projection GEMM + bias.  g_att[4096,1024] @ Wp[1024,1024] + b.
// ---------------------------------------------------------------------------
__global__ __launch_bounds__(256) void proj_gemm(const float* __restrict__ W,
                                                 const float* __restrict__ bias,
                                                 float* __restrict__ out) {
    __shared__ float As[16][68];
    __shared__ float Bs[16][68];
    const int tid = threadIdx.x;
    const int tx = tid & 15, ty = tid >> 4;
    const int row0 = blockIdx.y * 64;
    const int col0 = blockIdx.x * 64;

    const int am = tid >> 2;
    const int ak = (tid & 3) * 4;
    const int bk = tid >> 4;
    const int bn = (tid & 15) * 4;

    float acc[4][4] = {};

    for (int k0 = 0; k0 < CDIM; k0 += 16) {
        float4 a = *(const float4*)&g_att[(row0 + am) * CDIM + k0 + ak];
        As[ak + 0][am] = a.x; As[ak + 1][am] = a.y;
        As[ak + 2][am] = a.z; As[ak + 3][am] = a.w;
        *(float4*)&Bs[bk][bn] = *(const float4*)&W[(k0 + bk) * CDIM + col0 + bn];
        __syncthreads();
#pragma unroll
        for (int k = 0; k < 16; k++) {
            float4 ra = *(float4*)&As[k][ty * 4];
            float4 rb = *(float4*)&Bs[k][tx * 4];
            acc[0][0] += ra.x * rb.x; acc[0][1] += ra.x * rb.y; acc[0][2] += ra.x * rb.z; acc[0][3] += ra.x * rb.w;
            acc[1][0] += ra.y * rb.x; acc[1][1] += ra.y * rb.y; acc[1][2] += ra.y * rb.z; acc[1][3] += ra.y * rb.w;
            acc[2][0] += ra.z * rb.x; acc[2][1] += ra.z * rb.y; acc[2][2] += ra.z * rb.z; acc[2][3] += ra.z * rb.w;
            acc[3][0] += ra.w * rb.x; acc[3][1] += ra.w * rb.y; acc[3][2] += ra.w * rb.z; acc[3][3] += ra.w * rb.w;
        }
        __syncthreads();
    }

#pragma unroll
    for (int i = 0; i < 4; i++) {
        const int r = row0 + ty * 4 + i;
#pragma unroll
        for (int j = 0; j < 4; j++) {
            const int c = col0 + tx * 4 + j;
            out[r * CDIM + c] = acc[i][j] + bias[c];
        }
    }
}

// ---------------------------------------------------------------------------
extern "C" void kernel_launch(void* const* d_in, const int* in_sizes, int n_in,
                              void* d_out, int out_size) {
    const float* x      = (const float*)d_in[0];
    const float* w_qkv  = (const float*)d_in[1];
    const float* w_proj = (const float*)d_in[2];
    const float* b_proj = (const float*)d_in[3];
    float* out = (float*)d_out;

    (void)in_sizes; (void)n_in; (void)out_size;

    const size_t attn_smem = (3 * 64 * 68 + 3 * 64 + 64 * 4) * sizeof(float);
    cudaFuncSetAttribute(attn_kernel, cudaFuncAttributeMaxDynamicSharedMemorySize,
                         (int)attn_smem);

    qkv_gemm<<<dim3(QKV_N / 64, MROWS / 64), 256>>>(x, w_qkv);
    attn_kernel<<<dim3(SEQ / 64, BATCH * HEADS), 256, attn_smem>>>();
    proj_gemm<<<dim3(CDIM / 64, MROWS / 64), 256>>>(w_proj, b_proj, out);
}